// round 9
// baseline (speedup 1.0000x reference)
#include <cuda_runtime.h>
#include <stdint.h>

#define EPS 1e-5f

typedef unsigned long long ull;

// ---------------- scratch (static device globals; no allocation) ------------
__device__ uint32_t g_A[256 * 600 * 24];     // stage-1 sign bits: (b,h) -> 760 bits (p = w*40 + c1)
__device__ uint32_t g_W2[40 * 24];           // conv2 weight signs, same bit order
__device__ uint32_t g_FC1[80 * 49];          // fc1 weight signs (1560 bits)
__device__ uint32_t g_FC2[2 * 3];            // fc2 weight signs (80 bits)
__device__ uint32_t g_ticket;                // ka work queue (reset by kw_pack)

// ---------------- f32x2 helpers ----------------------------------------------
__device__ __forceinline__ ull pk2(float lo, float hi) {
    ull r; asm("mov.b64 %0, {%1,%2};" : "=l"(r) : "f"(lo), "f"(hi)); return r;
}
__device__ __forceinline__ ull fma2(ull a, ull b, ull c) {
    ull d; asm("fma.rn.f32x2 %0, %1, %2, %3;" : "=l"(d) : "l"(a), "l"(b), "l"(c)); return d;
}
__device__ __forceinline__ ull mul2(ull a, ull b) {
    ull d; asm("mul.rn.f32x2 %0, %1, %2;" : "=l"(d) : "l"(a), "l"(b)); return d;
}
__device__ __forceinline__ ull add2(ull a, ull b) {
    ull d; asm("add.rn.f32x2 %0, %1, %2;" : "=l"(d) : "l"(a), "l"(b)); return d;
}

// ---------------- kernel W: pack binary weights (warp-ballot, full chip) ----
__global__ void kw_pack(const float* __restrict__ w2,
                        const float* __restrict__ fc1,
                        const float* __restrict__ fc2) {
    if (blockIdx.x == 0 && threadIdx.x == 0) g_ticket = 0;   // reset ka work queue
    int gwid = (blockIdx.x * blockDim.x + threadIdx.x) >> 5;
    int lane = threadIdx.x & 31;

    if (gwid < 960) {                        // conv2: 40 rows x 24 words
        int c2 = gwid / 24, k = gwid % 24;
        int p = 32 * k + lane;               // bit p = kw*40 + c1
        bool bit = false;
        if (p < 760) {
            int kw = p / 40, c1 = p % 40;
            bit = w2[(c2 * 40 + c1) * 19 + kw] > 0.f;
        }
        uint32_t word = __ballot_sync(0xFFFFFFFFu, bit);
        if (lane == 0) g_W2[gwid] = word;
    } else if (gwid < 960 + 3920) {          // fc1: 80 rows x 49 words
        int i = gwid - 960;
        int o = i / 49, k = i % 49;
        int idx = 32 * k + lane;
        bool bit = (idx < 1560) && (fc1[o * 1560 + idx] > 0.f);
        uint32_t word = __ballot_sync(0xFFFFFFFFu, bit);
        if (lane == 0) g_FC1[i] = word;
    } else if (gwid < 960 + 3920 + 6) {      // fc2: 2 rows x 3 words
        int i = gwid - (960 + 3920);
        int o = i / 3, k = i % 3;
        int idx = 32 * k + lane;
        bool bit = (idx < 80) && (fc2[o * 80 + idx] > 0.f);
        uint32_t word = __ballot_sync(0xFFFFFFFFu, bit);
        if (lane == 0) g_FC2[i] = word;
    }
}

// ---------------- kernel A: persistent conv1 + BN1 + sign + bitpack ---------
// Grid = 592 (148 SM x occ 4), one wave. Each block stages weights ONCE, then
// pulls 60-row chunks via atomic ticket (2560 total). Inner compute identical
// to the 198.9us champion: channels in pairs (c1, c1+20) in f32x2 lanes,
// t-ascending rn-FMA (bit-identical to scalar direct conv), vector BN epilogue
// (lane == __fmul_rn/__fadd_rn), sign via signed-int compare on raw bits.
__global__ __launch_bounds__(96, 4) void ka_conv1(
    const float* __restrict__ x, const float* __restrict__ w1,
    const float* __restrict__ bg, const float* __restrict__ bbv,
    const float* __restrict__ bm, const float* __restrict__ bv) {
    __shared__ float xs[88 * 19];
    __shared__ ull wsp[20 * 29];            // packed sign pairs (c1, c1+20)
    __shared__ ull scp[20], sbp[20];        // packed BN scale/shift pairs
    __shared__ uint32_t outw[60 * 24];
    __shared__ int sticket;

    int tid = threadIdx.x;

    // ---- stage weights + BN constants once per block ----
    for (int idx = tid; idx < 20 * 29; idx += 96) {
        int p = idx / 29, t = idx % 29;
        float lo = (w1[p * 29 + t] > 0.f) ? 1.f : -1.f;
        float hi = (w1[(p + 20) * 29 + t] > 0.f) ? 1.f : -1.f;
        wsp[idx] = pk2(lo, hi);
    }
    if (tid < 20) {
        float sclo = bg[tid] / sqrtf(bv[tid] + EPS);
        float schi = bg[tid + 20] / sqrtf(bv[tid + 20] + EPS);
        scp[tid] = pk2(sclo, schi);
        sbp[tid] = pk2(__fsub_rn(bbv[tid], __fmul_rn(bm[tid], sclo)),
                       __fsub_rn(bbv[tid + 20], __fmul_rn(bm[tid + 20], schi)));
    }

    int w = tid % 19;
    int slot = tid / 19;                     // 0..4 (tid 95 inactive in compute)
    bool active = (tid < 95);

    while (true) {
        __syncthreads();                     // guards outw reuse + sticket slot
        if (tid == 0) sticket = atomicAdd(&g_ticket, 1);
        __syncthreads();
        int t = sticket;
        if (t >= 2560) break;
        int b = t / 10;
        int h0 = (t % 10) * 60;

        for (int idx = tid; idx < 88 * 19; idx += 96) {
            int r = idx / 19, c = idx % 19;
            int gh = h0 - 14 + r;
            xs[idx] = (gh >= 0 && gh < 600) ? x[(b * 600 + gh) * 19 + c] : 0.f;
        }
        for (int idx = tid; idx < 60 * 24; idx += 96) outw[idx] = 0;
        __syncthreads();

        if (active) {
            ull xd[40];
            #pragma unroll
            for (int i = 0; i < 40; i++) {
                float v = xs[(slot * 12 + i) * 19 + w];
                xd[i] = pk2(v, v);
            }

            uint32_t m0[12], m1[12];
            #pragma unroll
            for (int j = 0; j < 12; j++) { m0[j] = 0u; m1[j] = 0u; }

            for (int pair = 0; pair < 20; pair++) {
                ull acc[12];
                #pragma unroll
                for (int j = 0; j < 12; j++) acc[j] = 0ull;   // (+0.f, +0.f)
                #pragma unroll
                for (int tt = 0; tt < 29; tt++) {             // sequential tap order
                    ull s2 = wsp[pair * 29 + tt];
                    #pragma unroll
                    for (int j = 0; j < 12; j++) acc[j] = fma2(s2, xd[tt + j], acc[j]);
                }
                ull sc2 = scp[pair], sb2 = sbp[pair];
                #pragma unroll
                for (int j = 0; j < 12; j++) {
                    ull y2 = add2(mul2(acc[j], sc2), sb2);    // lane == __fadd_rn(__fmul_rn(..))
                    int ylo = (int)(uint32_t)y2;              // raw float bits: >0 signed <=> y>0
                    int yhi = (int)(uint32_t)(y2 >> 32);
                    m0[j] |= ((uint32_t)(ylo > 0)) << pair;
                    m1[j] |= ((uint32_t)(yhi > 0)) << pair;
                }
            }
            // pack: bits [w*40, w*40+40) span 2 u32 words (w*40 % 32 in {0,8,16,24})
            int b0 = w * 40;
            int wi = b0 >> 5, sh = b0 & 31;
            #pragma unroll
            for (int j = 0; j < 12; j++) {
                ull mask = (ull)m0[j] | ((ull)m1[j] << 20);
                int row = slot * 12 + j;
                atomicOr(&outw[row * 24 + wi], (uint32_t)(mask << sh));
                atomicOr(&outw[row * 24 + wi + 1], (uint32_t)(mask >> (32 - sh)));
            }
        }
        __syncthreads();
        for (int idx = tid; idx < 60 * 24; idx += 96)
            g_A[(b * 600 + h0) * 24 + idx] = outw[idx];
    }
}

// ---------------- kernel B: binary conv2 + BN2 + PReLU + pool + FC1/BN3/FC2 -
// Block per batch; two 20-channel passes (pbuf 20x600 = 48KB -> 3 blocks/SM).
// Within a pass each thread covers 2 h-rows per weight fetch (A bits in regs,
// conv2 weights LDS-broadcast once per (2h, c)). Pool summed ascending.
__global__ __launch_bounds__(256) void kb_conv2(
    const float* __restrict__ bg, const float* __restrict__ bbv,
    const float* __restrict__ bm, const float* __restrict__ bv,
    const float* __restrict__ a2,
    const float* __restrict__ g3, const float* __restrict__ b3,
    const float* __restrict__ m3, const float* __restrict__ v3,
    float* __restrict__ out) {
    extern __shared__ uint32_t sm[];
    float*    pbuf = (float*)sm;                  // 20*600 floats (48000 B)
    uint32_t* w2p  = sm + 12000;                  // 960 u32 (8B-aligned)
    uint32_t* fcw  = w2p + 960;                   // 3920 u32
    float*    ssc  = (float*)(fcw + 3920);        // 40
    float*    ssb  = ssc + 40;                    // 40
    float*    sc3  = ssb + 40;                    // 80
    float*    sb3  = sc3 + 80;                    // 80
    uint32_t* outm = (uint32_t*)(sb3 + 80);       // 49 (pad to 52)
    uint32_t* hb   = outm + 52;                   // 3

    int tid = threadIdx.x;
    int b = blockIdx.x;

    for (int idx = tid; idx < 960; idx += 256) w2p[idx] = g_W2[idx];
    for (int idx = tid; idx < 3920; idx += 256) fcw[idx] = g_FC1[idx];
    if (tid < 40) {
        float sc = bg[tid] / sqrtf(bv[tid] + EPS);
        ssc[tid] = sc;
        ssb[tid] = __fsub_rn(bbv[tid], __fmul_rn(bm[tid], sc));
    }
    if (tid < 80) {
        float sc = g3[tid] / sqrtf(v3[tid] + EPS);
        sc3[tid] = sc;
        sb3[tid] = __fsub_rn(b3[tid], __fmul_rn(m3[tid], sc));
    }
    if (tid < 52) outm[tid] = 0;
    float av = a2[0];
    __syncthreads();

    const ull* arow_base = (const ull*)(g_A + b * 600 * 24);
    const ull* w2p64 = (const ull*)w2p;

    #pragma unroll
    for (int p = 0; p < 2; p++) {
        // rows 0..511: thread covers h1 = tid, h2 = tid + 256
        {
            int h1 = tid, h2 = tid + 256;
            ull ab1[12], ab2[12];
            const ull* ar1 = arow_base + h1 * 12;
            const ull* ar2 = arow_base + h2 * 12;
            #pragma unroll
            for (int k = 0; k < 12; k++) { ab1[k] = __ldg(&ar1[k]); ab2[k] = __ldg(&ar2[k]); }
            #pragma unroll 4
            for (int c = 0; c < 20; c++) {
                int c2 = p * 20 + c;
                const ull* wr = w2p64 + c2 * 12;
                int cnt1 = 0, cnt2 = 0;
                #pragma unroll
                for (int k = 0; k < 12; k++) {
                    ull wv = wr[k];
                    cnt1 += __popcll(ab1[k] ^ wv);
                    cnt2 += __popcll(ab2[k] ^ wv);
                }
                float sc = ssc[c2], sb = ssb[c2];
                float y1 = __fadd_rn(__fmul_rn((float)(760 - 2 * cnt1), sc), sb);
                float y2 = __fadd_rn(__fmul_rn((float)(760 - 2 * cnt2), sc), sb);
                pbuf[c * 600 + h1] = (y1 >= 0.f) ? y1 : __fmul_rn(av, y1);
                pbuf[c * 600 + h2] = (y2 >= 0.f) ? y2 : __fmul_rn(av, y2);
            }
        }
        // rows 512..599: threads 0..87
        if (tid < 88) {
            int h = 512 + tid;
            ull ab[12];
            const ull* ar = arow_base + h * 12;
            #pragma unroll
            for (int k = 0; k < 12; k++) ab[k] = __ldg(&ar[k]);
            #pragma unroll 4
            for (int c = 0; c < 20; c++) {
                int c2 = p * 20 + c;
                const ull* wr = w2p64 + c2 * 12;
                int cnt = 0;
                #pragma unroll
                for (int k = 0; k < 12; k++) cnt += __popcll(ab[k] ^ wr[k]);
                float y = __fadd_rn(__fmul_rn((float)(760 - 2 * cnt), ssc[c2]), ssb[c2]);
                pbuf[c * 600 + h] = (y >= 0.f) ? y : __fmul_rn(av, y);
            }
        }
        __syncthreads();
        // pooling: 20 channels x 39 windows, each summed ascending
        for (int idx = tid; idx < 20 * 39; idx += 256) {
            int c = idx / 39, j = idx % 39;
            const float* pw = pbuf + c * 600 + 15 * j;
            float s = 0.f;
            #pragma unroll 1
            for (int i = 0; i < 30; i++) s = __fadd_rn(s, pw[i]);
            if (s > 0.f) {
                int bit = (p * 20 + c) * 39 + j;               // flat index in 1560
                atomicOr(&outm[bit >> 5], 1u << (bit & 31));
            }
        }
        __syncthreads();
    }

    // fused FC1 + BN3 + sign + FC2
    bool bit = false;
    if (tid < 80) {
        int cnt = 0;
        #pragma unroll
        for (int k = 0; k < 49; k++) cnt += __popc(outm[k] ^ fcw[tid * 49 + k]);
        int dot = 1560 - 2 * cnt;                              // exact integer
        float y = __fadd_rn(__fmul_rn((float)dot, sc3[tid]), sb3[tid]);
        bit = (y > 0.f);                                       // sign(prelu(y)) = sign(y)
    }
    uint32_t bl = __ballot_sync(0xFFFFFFFFu, bit);
    if ((tid & 31) == 0 && tid < 96) hb[tid >> 5] = bl;
    __syncthreads();

    if (tid < 2) {
        int cnt = 0;
        #pragma unroll
        for (int k = 0; k < 3; k++) cnt += __popc(hb[k] ^ g_FC2[tid * 3 + k]);
        out[b * 2 + tid] = (float)(80 - 2 * cnt);              // exact integer
    }
}

// ---------------- launch -----------------------------------------------------
extern "C" void kernel_launch(void* const* d_in, const int* in_sizes, int n_in,
                              void* d_out, int out_size) {
    const float* x    = (const float*)d_in[0];
    const float* w1   = (const float*)d_in[1];
    const float* bn1g = (const float*)d_in[2];
    const float* bn1b = (const float*)d_in[3];
    const float* bn1m = (const float*)d_in[4];
    const float* bn1v = (const float*)d_in[5];
    const float* w2   = (const float*)d_in[7];
    const float* bn2g = (const float*)d_in[8];
    const float* bn2b = (const float*)d_in[9];
    const float* bn2m = (const float*)d_in[10];
    const float* bn2v = (const float*)d_in[11];
    const float* a2   = (const float*)d_in[12];
    const float* fc1  = (const float*)d_in[13];
    const float* bn3g = (const float*)d_in[14];
    const float* bn3b = (const float*)d_in[15];
    const float* bn3m = (const float*)d_in[16];
    const float* bn3v = (const float*)d_in[17];
    const float* fc2  = (const float*)d_in[19];
    float* out = (float*)d_out;

    int nwords = 960 + 3920 + 6;
    int nthreads = nwords * 32;
    kw_pack<<<(nthreads + 255) / 256, 256>>>(w2, fc1, fc2);

    ka_conv1<<<592, 96>>>(x, w1, bn1g, bn1b, bn1m, bn1v);

    size_t smemB = (size_t)(12000 + 960 + 3920 + 40 + 40 + 80 + 80 + 52 + 4) * 4;
    cudaFuncSetAttribute(kb_conv2, cudaFuncAttributeMaxDynamicSharedMemorySize, (int)smemB);
    kb_conv2<<<256, 256, smemB>>>(bn2g, bn2b, bn2m, bn2v, a2,
                                  bn3g, bn3b, bn3m, bn3v, out);
}

// round 10
// speedup vs baseline: 1.0816x; 1.0816x over previous
#include <cuda_runtime.h>
#include <stdint.h>

#define EPS 1e-5f

typedef unsigned long long ull;

// ---------------- scratch (static device globals; no allocation) ------------
__device__ uint32_t g_A[256 * 600 * 24];     // stage-1 sign bits: (b,h) -> 760 bits (p = w*40 + c1)
__device__ uint32_t g_W2[40 * 24];           // conv2 weight signs, same bit order
__device__ uint32_t g_FC1[80 * 49];          // fc1 weight signs (1560 bits)
__device__ uint32_t g_FC2[2 * 3];            // fc2 weight signs (80 bits)

// ---------------- f32x2 helpers ----------------------------------------------
__device__ __forceinline__ ull pk2(float lo, float hi) {
    ull r; asm("mov.b64 %0, {%1,%2};" : "=l"(r) : "f"(lo), "f"(hi)); return r;
}
__device__ __forceinline__ ull fma2(ull a, ull b, ull c) {
    ull d; asm("fma.rn.f32x2 %0, %1, %2, %3;" : "=l"(d) : "l"(a), "l"(b), "l"(c)); return d;
}
__device__ __forceinline__ ull mul2(ull a, ull b) {
    ull d; asm("mul.rn.f32x2 %0, %1, %2;" : "=l"(d) : "l"(a), "l"(b)); return d;
}
__device__ __forceinline__ ull add2(ull a, ull b) {
    ull d; asm("add.rn.f32x2 %0, %1, %2;" : "=l"(d) : "l"(a), "l"(b)); return d;
}

// ---------------- kernel A: weight-pack prologue blocks + conv1 blocks ------
// Grid = 2580 x 96 threads.
//   blocks 0..19   : warp-ballot packing of w2/fc1/fc2 signs (60 warps total,
//                    ~82 words each; grid-parallel, scheduled in wave 1).
//   blocks 20..2579: conv1 + BN1 + sign + bitpack, 60-row chunks — byte-
//                    identical to the 198.9us champion (channel pairs in f32x2
//                    lanes, t-ascending rn-FMA == scalar direct conv, vector
//                    BN epilogue lane == __fmul_rn/__fadd_rn, integer sign).
__global__ __launch_bounds__(96, 4) void ka_conv1(
    const float* __restrict__ x, const float* __restrict__ w1,
    const float* __restrict__ bg, const float* __restrict__ bbv,
    const float* __restrict__ bm, const float* __restrict__ bv,
    const float* __restrict__ w2f, const float* __restrict__ fc1f,
    const float* __restrict__ fc2f) {
    __shared__ float xs[88 * 19];
    __shared__ ull wsp[20 * 29];            // packed sign pairs (c1, c1+20)
    __shared__ ull scp[20], sbp[20];        // packed BN scale/shift pairs
    __shared__ uint32_t outw[60 * 24];

    int tid = threadIdx.x;
    int bid = blockIdx.x;

    if (bid < 20) {
        // ---- weight packing (same word layout as the standalone kw_pack) ----
        int gw = bid * 3 + (tid >> 5);       // 0..59
        int lane = tid & 31;
        for (int wd = gw; wd < 4886; wd += 60) {
            if (wd < 960) {                  // conv2: 40 rows x 24 words
                int c2 = wd / 24, k = wd % 24;
                int p = 32 * k + lane;       // bit p = kw*40 + c1
                bool bit = false;
                if (p < 760) bit = w2f[(c2 * 40 + (p % 40)) * 19 + (p / 40)] > 0.f;
                uint32_t word = __ballot_sync(0xFFFFFFFFu, bit);
                if (lane == 0) g_W2[wd] = word;
            } else if (wd < 4880) {          // fc1: 80 rows x 49 words
                int i = wd - 960;
                int o = i / 49, k = i % 49;
                int idx = 32 * k + lane;
                bool bit = (idx < 1560) && (fc1f[o * 1560 + idx] > 0.f);
                uint32_t word = __ballot_sync(0xFFFFFFFFu, bit);
                if (lane == 0) g_FC1[i] = word;
            } else {                         // fc2: 2 rows x 3 words
                int i = wd - 4880;
                int o = i / 3, k = i % 3;
                int idx = 32 * k + lane;
                bool bit = (idx < 80) && (fc2f[o * 80 + idx] > 0.f);
                uint32_t word = __ballot_sync(0xFFFFFFFFu, bit);
                if (lane == 0) g_FC2[i] = word;
            }
        }
        return;
    }

    // ---- conv1 block ----
    int t = bid - 20;
    int h0 = (t % 10) * 60;
    int b = t / 10;

    for (int idx = tid; idx < 88 * 19; idx += 96) {
        int r = idx / 19, c = idx % 19;
        int gh = h0 - 14 + r;
        xs[idx] = (gh >= 0 && gh < 600) ? x[(b * 600 + gh) * 19 + c] : 0.f;
    }
    for (int idx = tid; idx < 20 * 29; idx += 96) {
        int p = idx / 29, tt = idx % 29;
        float lo = (w1[p * 29 + tt] > 0.f) ? 1.f : -1.f;
        float hi = (w1[(p + 20) * 29 + tt] > 0.f) ? 1.f : -1.f;
        wsp[idx] = pk2(lo, hi);
    }
    if (tid < 20) {
        float sclo = bg[tid] / sqrtf(bv[tid] + EPS);
        float schi = bg[tid + 20] / sqrtf(bv[tid + 20] + EPS);
        scp[tid] = pk2(sclo, schi);
        sbp[tid] = pk2(__fsub_rn(bbv[tid], __fmul_rn(bm[tid], sclo)),
                       __fsub_rn(bbv[tid + 20], __fmul_rn(bm[tid + 20], schi)));
    }
    for (int idx = tid; idx < 60 * 24; idx += 96) outw[idx] = 0;
    __syncthreads();

    if (tid < 95) {
        int w = tid % 19;
        int slot = tid / 19;                 // 0..4, 12 rows each
        ull xd[40];
        #pragma unroll
        for (int i = 0; i < 40; i++) {
            float v = xs[(slot * 12 + i) * 19 + w];
            xd[i] = pk2(v, v);
        }

        uint32_t m0[12], m1[12];
        #pragma unroll
        for (int j = 0; j < 12; j++) { m0[j] = 0u; m1[j] = 0u; }

        for (int pair = 0; pair < 20; pair++) {
            ull acc[12];
            #pragma unroll
            for (int j = 0; j < 12; j++) acc[j] = 0ull;   // (+0.f, +0.f)
            #pragma unroll
            for (int tt = 0; tt < 29; tt++) {             // sequential tap order
                ull s2 = wsp[pair * 29 + tt];
                #pragma unroll
                for (int j = 0; j < 12; j++) acc[j] = fma2(s2, xd[tt + j], acc[j]);
            }
            ull sc2 = scp[pair], sb2 = sbp[pair];
            #pragma unroll
            for (int j = 0; j < 12; j++) {
                ull y2 = add2(mul2(acc[j], sc2), sb2);    // lane == __fadd_rn(__fmul_rn(..))
                int ylo = (int)(uint32_t)y2;              // raw float bits: >0 signed <=> y>0
                int yhi = (int)(uint32_t)(y2 >> 32);
                m0[j] |= ((uint32_t)(ylo > 0)) << pair;
                m1[j] |= ((uint32_t)(yhi > 0)) << pair;
            }
        }
        // pack: bits [w*40, w*40+40) span exactly 2 u32 words (w*40 % 32 in {0,8,16,24})
        int b0 = w * 40;
        int wi = b0 >> 5, sh = b0 & 31;
        #pragma unroll
        for (int j = 0; j < 12; j++) {
            ull mask = (ull)m0[j] | ((ull)m1[j] << 20);
            int row = slot * 12 + j;
            atomicOr(&outw[row * 24 + wi], (uint32_t)(mask << sh));
            atomicOr(&outw[row * 24 + wi + 1], (uint32_t)(mask >> (32 - sh)));
        }
    }
    __syncthreads();
    for (int idx = tid; idx < 60 * 24; idx += 96)
        g_A[(b * 600 + h0) * 24 + idx] = outw[idx];
}

// ---------------- kernel B: binary conv2 + BN2 + PReLU + pool + FC1/BN3/FC2 -
// Block per batch; two 20-channel passes (pbuf 20x600 = 48KB -> 3 blocks/SM).
// Within a pass each thread covers 2 h-rows per weight fetch (A bits in regs,
// conv2 weights LDS-broadcast once per (2h, c)). Pool summed ascending.
__global__ __launch_bounds__(256) void kb_conv2(
    const float* __restrict__ bg, const float* __restrict__ bbv,
    const float* __restrict__ bm, const float* __restrict__ bv,
    const float* __restrict__ a2,
    const float* __restrict__ g3, const float* __restrict__ b3,
    const float* __restrict__ m3, const float* __restrict__ v3,
    float* __restrict__ out) {
    extern __shared__ uint32_t sm[];
    float*    pbuf = (float*)sm;                  // 20*600 floats (48000 B)
    uint32_t* w2p  = sm + 12000;                  // 960 u32 (8B-aligned)
    uint32_t* fcw  = w2p + 960;                   // 3920 u32
    float*    ssc  = (float*)(fcw + 3920);        // 40
    float*    ssb  = ssc + 40;                    // 40
    float*    sc3  = ssb + 40;                    // 80
    float*    sb3  = sc3 + 80;                    // 80
    uint32_t* outm = (uint32_t*)(sb3 + 80);       // 49 (pad to 52)
    uint32_t* hb   = outm + 52;                   // 3

    int tid = threadIdx.x;
    int b = blockIdx.x;

    for (int idx = tid; idx < 960; idx += 256) w2p[idx] = g_W2[idx];
    for (int idx = tid; idx < 3920; idx += 256) fcw[idx] = g_FC1[idx];
    if (tid < 40) {
        float sc = bg[tid] / sqrtf(bv[tid] + EPS);
        ssc[tid] = sc;
        ssb[tid] = __fsub_rn(bbv[tid], __fmul_rn(bm[tid], sc));
    }
    if (tid < 80) {
        float sc = g3[tid] / sqrtf(v3[tid] + EPS);
        sc3[tid] = sc;
        sb3[tid] = __fsub_rn(b3[tid], __fmul_rn(m3[tid], sc));
    }
    if (tid < 52) outm[tid] = 0;
    float av = a2[0];
    __syncthreads();

    const ull* arow_base = (const ull*)(g_A + b * 600 * 24);
    const ull* w2p64 = (const ull*)w2p;

    #pragma unroll
    for (int p = 0; p < 2; p++) {
        // rows 0..511: thread covers h1 = tid, h2 = tid + 256
        {
            int h1 = tid, h2 = tid + 256;
            ull ab1[12], ab2[12];
            const ull* ar1 = arow_base + h1 * 12;
            const ull* ar2 = arow_base + h2 * 12;
            #pragma unroll
            for (int k = 0; k < 12; k++) { ab1[k] = __ldg(&ar1[k]); ab2[k] = __ldg(&ar2[k]); }
            #pragma unroll 4
            for (int c = 0; c < 20; c++) {
                int c2 = p * 20 + c;
                const ull* wr = w2p64 + c2 * 12;
                int cnt1 = 0, cnt2 = 0;
                #pragma unroll
                for (int k = 0; k < 12; k++) {
                    ull wv = wr[k];
                    cnt1 += __popcll(ab1[k] ^ wv);
                    cnt2 += __popcll(ab2[k] ^ wv);
                }
                float sc = ssc[c2], sb = ssb[c2];
                float y1 = __fadd_rn(__fmul_rn((float)(760 - 2 * cnt1), sc), sb);
                float y2 = __fadd_rn(__fmul_rn((float)(760 - 2 * cnt2), sc), sb);
                pbuf[c * 600 + h1] = (y1 >= 0.f) ? y1 : __fmul_rn(av, y1);
                pbuf[c * 600 + h2] = (y2 >= 0.f) ? y2 : __fmul_rn(av, y2);
            }
        }
        // rows 512..599: threads 0..87
        if (tid < 88) {
            int h = 512 + tid;
            ull ab[12];
            const ull* ar = arow_base + h * 12;
            #pragma unroll
            for (int k = 0; k < 12; k++) ab[k] = __ldg(&ar[k]);
            #pragma unroll 4
            for (int c = 0; c < 20; c++) {
                int c2 = p * 20 + c;
                const ull* wr = w2p64 + c2 * 12;
                int cnt = 0;
                #pragma unroll
                for (int k = 0; k < 12; k++) cnt += __popcll(ab[k] ^ wr[k]);
                float y = __fadd_rn(__fmul_rn((float)(760 - 2 * cnt), ssc[c2]), ssb[c2]);
                pbuf[c * 600 + h] = (y >= 0.f) ? y : __fmul_rn(av, y);
            }
        }
        __syncthreads();
        // pooling: 20 channels x 39 windows, each summed ascending
        for (int idx = tid; idx < 20 * 39; idx += 256) {
            int c = idx / 39, j = idx % 39;
            const float* pw = pbuf + c * 600 + 15 * j;
            float s = 0.f;
            #pragma unroll 1
            for (int i = 0; i < 30; i++) s = __fadd_rn(s, pw[i]);
            if (s > 0.f) {
                int bit = (p * 20 + c) * 39 + j;               // flat index in 1560
                atomicOr(&outm[bit >> 5], 1u << (bit & 31));
            }
        }
        __syncthreads();
    }

    // fused FC1 + BN3 + sign + FC2
    bool bit = false;
    if (tid < 80) {
        int cnt = 0;
        #pragma unroll
        for (int k = 0; k < 49; k++) cnt += __popc(outm[k] ^ fcw[tid * 49 + k]);
        int dot = 1560 - 2 * cnt;                              // exact integer
        float y = __fadd_rn(__fmul_rn((float)dot, sc3[tid]), sb3[tid]);
        bit = (y > 0.f);                                       // sign(prelu(y)) = sign(y)
    }
    uint32_t bl = __ballot_sync(0xFFFFFFFFu, bit);
    if ((tid & 31) == 0 && tid < 96) hb[tid >> 5] = bl;
    __syncthreads();

    if (tid < 2) {
        int cnt = 0;
        #pragma unroll
        for (int k = 0; k < 3; k++) cnt += __popc(hb[k] ^ g_FC2[tid * 3 + k]);
        out[b * 2 + tid] = (float)(80 - 2 * cnt);              // exact integer
    }
}

// ---------------- launch -----------------------------------------------------
extern "C" void kernel_launch(void* const* d_in, const int* in_sizes, int n_in,
                              void* d_out, int out_size) {
    const float* x    = (const float*)d_in[0];
    const float* w1   = (const float*)d_in[1];
    const float* bn1g = (const float*)d_in[2];
    const float* bn1b = (const float*)d_in[3];
    const float* bn1m = (const float*)d_in[4];
    const float* bn1v = (const float*)d_in[5];
    const float* w2   = (const float*)d_in[7];
    const float* bn2g = (const float*)d_in[8];
    const float* bn2b = (const float*)d_in[9];
    const float* bn2m = (const float*)d_in[10];
    const float* bn2v = (const float*)d_in[11];
    const float* a2   = (const float*)d_in[12];
    const float* fc1  = (const float*)d_in[13];
    const float* bn3g = (const float*)d_in[14];
    const float* bn3b = (const float*)d_in[15];
    const float* bn3m = (const float*)d_in[16];
    const float* bn3v = (const float*)d_in[17];
    const float* fc2  = (const float*)d_in[19];
    float* out = (float*)d_out;

    // 20 pack blocks + 2560 conv blocks in one launch
    ka_conv1<<<2580, 96>>>(x, w1, bn1g, bn1b, bn1m, bn1v, w2, fc1, fc2);

    size_t smemB = (size_t)(12000 + 960 + 3920 + 40 + 40 + 80 + 80 + 52 + 4) * 4;
    cudaFuncSetAttribute(kb_conv2, cudaFuncAttributeMaxDynamicSharedMemorySize, (int)smemB);
    kb_conv2<<<256, 256, smemB>>>(bn2g, bn2b, bn2m, bn2v, a2,
                                  bn3g, bn3b, bn3m, bn3v, out);
}

// round 11
// speedup vs baseline: 1.0934x; 1.0109x over previous
#include <cuda_runtime.h>
#include <stdint.h>

#define EPS 1e-5f

typedef unsigned long long ull;

// ---------------- scratch (static device globals; no allocation) ------------
__device__ uint32_t g_A[256 * 600 * 24];     // stage-1 sign bits: (b,h) -> 760 bits (p = w*40 + c1)
__device__ uint32_t g_W2[40 * 24];           // conv2 weight signs
__device__ uint32_t g_FC1[80 * 80];          // fc1 signs, 2 words per channel: [o][2c+half]
                                             //   half 0: bits 0..19 = windows j 0..19
                                             //   half 1: bits 0..18 = windows j 20..38
__device__ uint32_t g_FC2[2 * 3];            // fc2 weight signs (80 bits)
__device__ uint32_t g_PB[256 * 80];          // pooled sign bits, same 2-word/channel layout

// ---------------- f32x2 helpers ----------------------------------------------
__device__ __forceinline__ ull pk2(float lo, float hi) {
    ull r; asm("mov.b64 %0, {%1,%2};" : "=l"(r) : "f"(lo), "f"(hi)); return r;
}
__device__ __forceinline__ ull fma2(ull a, ull b, ull c) {
    ull d; asm("fma.rn.f32x2 %0, %1, %2, %3;" : "=l"(d) : "l"(a), "l"(b), "l"(c)); return d;
}
__device__ __forceinline__ ull mul2(ull a, ull b) {
    ull d; asm("mul.rn.f32x2 %0, %1, %2;" : "=l"(d) : "l"(a), "l"(b)); return d;
}
__device__ __forceinline__ ull add2(ull a, ull b) {
    ull d; asm("add.rn.f32x2 %0, %1, %2;" : "=l"(d) : "l"(a), "l"(b)); return d;
}

// ---------------- kernel A: weight-pack prologue blocks + conv1 blocks ------
// Grid = 2580 x 96. Blocks 0..19: warp-ballot packing (7366 words over 60
// warps, latency hidden under conv blocks). Blocks 20..2579: conv1 + BN1 +
// sign + bitpack, byte-identical math to the 198.9us champion.
__global__ __launch_bounds__(96, 4) void ka_conv1(
    const float* __restrict__ x, const float* __restrict__ w1,
    const float* __restrict__ bg, const float* __restrict__ bbv,
    const float* __restrict__ bm, const float* __restrict__ bv,
    const float* __restrict__ w2f, const float* __restrict__ fc1f,
    const float* __restrict__ fc2f) {
    __shared__ float xs[88 * 19];
    __shared__ ull wsp[20 * 29];            // packed sign pairs (c1, c1+20)
    __shared__ ull scp[20], sbp[20];        // packed BN scale/shift pairs
    __shared__ uint32_t outw[60 * 24];

    int tid = threadIdx.x;
    int bid = blockIdx.x;

    if (bid < 20) {
        int gw = bid * 3 + (tid >> 5);       // 0..59
        int lane = tid & 31;
        for (int wd = gw; wd < 7366; wd += 60) {
            if (wd < 960) {                  // conv2: 40 rows x 24 words
                int c2 = wd / 24, k = wd % 24;
                int p = 32 * k + lane;       // bit p = kw*40 + c1
                bool bit = false;
                if (p < 760) bit = w2f[(c2 * 40 + (p % 40)) * 19 + (p / 40)] > 0.f;
                uint32_t word = __ballot_sync(0xFFFFFFFFu, bit);
                if (lane == 0) g_W2[wd] = word;
            } else if (wd < 7360) {          // fc1: 80 rows x 80 words (split layout)
                int i = wd - 960;
                int o = i / 80, k = i % 80;
                int c = k >> 1, half = k & 1;
                bool valid = half ? (lane < 19) : (lane < 20);
                int j = half ? (20 + lane) : lane;
                bool bit = valid && (fc1f[o * 1560 + c * 39 + j] > 0.f);
                uint32_t word = __ballot_sync(0xFFFFFFFFu, bit);
                if (lane == 0) g_FC1[i] = word;
            } else {                         // fc2: 2 rows x 3 words
                int i = wd - 7360;
                int o = i / 3, k = i % 3;
                int idx = 32 * k + lane;
                bool bit = (idx < 80) && (fc2f[o * 80 + idx] > 0.f);
                uint32_t word = __ballot_sync(0xFFFFFFFFu, bit);
                if (lane == 0) g_FC2[i] = word;
            }
        }
        return;
    }

    // ---- conv1 block (unchanged from champion) ----
    int t = bid - 20;
    int h0 = (t % 10) * 60;
    int b = t / 10;

    for (int idx = tid; idx < 88 * 19; idx += 96) {
        int r = idx / 19, c = idx % 19;
        int gh = h0 - 14 + r;
        xs[idx] = (gh >= 0 && gh < 600) ? x[(b * 600 + gh) * 19 + c] : 0.f;
    }
    for (int idx = tid; idx < 20 * 29; idx += 96) {
        int p = idx / 29, tt = idx % 29;
        float lo = (w1[p * 29 + tt] > 0.f) ? 1.f : -1.f;
        float hi = (w1[(p + 20) * 29 + tt] > 0.f) ? 1.f : -1.f;
        wsp[idx] = pk2(lo, hi);
    }
    if (tid < 20) {
        float sclo = bg[tid] / sqrtf(bv[tid] + EPS);
        float schi = bg[tid + 20] / sqrtf(bv[tid + 20] + EPS);
        scp[tid] = pk2(sclo, schi);
        sbp[tid] = pk2(__fsub_rn(bbv[tid], __fmul_rn(bm[tid], sclo)),
                       __fsub_rn(bbv[tid + 20], __fmul_rn(bm[tid + 20], schi)));
    }
    for (int idx = tid; idx < 60 * 24; idx += 96) outw[idx] = 0;
    __syncthreads();

    if (tid < 95) {
        int w = tid % 19;
        int slot = tid / 19;                 // 0..4, 12 rows each
        ull xd[40];
        #pragma unroll
        for (int i = 0; i < 40; i++) {
            float v = xs[(slot * 12 + i) * 19 + w];
            xd[i] = pk2(v, v);
        }

        uint32_t m0[12], m1[12];
        #pragma unroll
        for (int j = 0; j < 12; j++) { m0[j] = 0u; m1[j] = 0u; }

        for (int pair = 0; pair < 20; pair++) {
            ull acc[12];
            #pragma unroll
            for (int j = 0; j < 12; j++) acc[j] = 0ull;   // (+0.f, +0.f)
            #pragma unroll
            for (int tt = 0; tt < 29; tt++) {             // sequential tap order
                ull s2 = wsp[pair * 29 + tt];
                #pragma unroll
                for (int j = 0; j < 12; j++) acc[j] = fma2(s2, xd[tt + j], acc[j]);
            }
            ull sc2 = scp[pair], sb2 = sbp[pair];
            #pragma unroll
            for (int j = 0; j < 12; j++) {
                ull y2 = add2(mul2(acc[j], sc2), sb2);    // lane == __fadd_rn(__fmul_rn(..))
                int ylo = (int)(uint32_t)y2;              // raw float bits: >0 signed <=> y>0
                int yhi = (int)(uint32_t)(y2 >> 32);
                m0[j] |= ((uint32_t)(ylo > 0)) << pair;
                m1[j] |= ((uint32_t)(yhi > 0)) << pair;
            }
        }
        int b0 = w * 40;
        int wi = b0 >> 5, sh = b0 & 31;
        #pragma unroll
        for (int j = 0; j < 12; j++) {
            ull mask = (ull)m0[j] | ((ull)m1[j] << 20);
            int row = slot * 12 + j;
            atomicOr(&outw[row * 24 + wi], (uint32_t)(mask << sh));
            atomicOr(&outw[row * 24 + wi + 1], (uint32_t)(mask >> (32 - sh)));
        }
    }
    __syncthreads();
    for (int idx = tid; idx < 60 * 24; idx += 96)
        g_A[(b * 600 + h0) * 24 + idx] = outw[idx];
}

// ---------------- kernel B: binary conv2 + BN2 + PReLU + pool (h-split) -----
// 512 blocks = 256 batches x 2 h-halves; one full wave at 4 blocks/SM.
// Half 0: rows 0..314 -> pool windows 0..19. Half 1: rows 300..599 -> 20..38.
// All 40 channels per block; pool bits -> g_PB words [b][2c+half] (disjoint).
__global__ __launch_bounds__(256) void kb_conv2(
    const float* __restrict__ bg, const float* __restrict__ bbv,
    const float* __restrict__ bm, const float* __restrict__ bv,
    const float* __restrict__ a2) {
    extern __shared__ uint32_t sm[];
    float*    pbuf = (float*)sm;                  // 40*316 floats (50560 B)
    uint32_t* w2p  = sm + 12640;                  // 960 u32 (8B-aligned)
    float*    ssc  = (float*)(w2p + 960);         // 40
    float*    ssb  = ssc + 40;                    // 40
    uint32_t* outm = (uint32_t*)(ssb + 40);       // 40

    int tid = threadIdx.x;
    int b = blockIdx.x >> 1;
    int half = blockIdx.x & 1;
    int r0 = half ? 300 : 0;
    int nrows = half ? 300 : 315;
    int nwin = half ? 19 : 20;

    for (int idx = tid; idx < 960; idx += 256) w2p[idx] = g_W2[idx];
    if (tid < 40) {
        float sc = bg[tid] / sqrtf(bv[tid] + EPS);
        ssc[tid] = sc;
        ssb[tid] = __fsub_rn(bbv[tid], __fmul_rn(bm[tid], sc));
        outm[tid] = 0;
    }
    float av = a2[0];
    __syncthreads();

    const ull* arow_base = (const ull*)g_A + (b * 600 + r0) * 12;
    const ull* w2p64 = (const ull*)w2p;

    for (int hl = tid; hl < nrows; hl += 256) {
        ull ab[12];
        const ull* ar = arow_base + hl * 12;
        #pragma unroll
        for (int k = 0; k < 12; k++) ab[k] = __ldg(&ar[k]);
        #pragma unroll 4
        for (int c2 = 0; c2 < 40; c2++) {
            const ull* wr = w2p64 + c2 * 12;
            int cnt = 0;
            #pragma unroll
            for (int k = 0; k < 12; k++) cnt += __popcll(ab[k] ^ wr[k]);
            float y = __fadd_rn(__fmul_rn((float)(760 - 2 * cnt), ssc[c2]), ssb[c2]);
            pbuf[c2 * 316 + hl] = (y >= 0.f) ? y : __fmul_rn(av, y);
        }
    }
    __syncthreads();

    // pooling: 40 channels x nwin windows, each summed ascending
    for (int idx = tid; idx < 40 * nwin; idx += 256) {
        int c = idx / nwin, jj = idx % nwin;
        int j = (half ? 20 : 0) + jj;
        const float* pw = pbuf + c * 316 + (15 * j - r0);
        float s = 0.f;
        #pragma unroll 1
        for (int i = 0; i < 30; i++) s = __fadd_rn(s, pw[i]);
        if (s > 0.f) atomicOr(&outm[c], 1u << jj);
    }
    __syncthreads();
    if (tid < 40) g_PB[b * 80 + tid * 2 + half] = outm[tid];
}

// ---------------- kernel C: binary FC1 + BN3 + sign + binary FC2 ------------
// 256 blocks x 128 threads. fcw rows read directly from L2 (no smem staging).
__global__ __launch_bounds__(128) void kc_fc(
    const float* __restrict__ g3, const float* __restrict__ b3,
    const float* __restrict__ m3, const float* __restrict__ v3,
    float* __restrict__ out) {
    __shared__ uint32_t pb[80];
    __shared__ uint32_t hb[3];
    int tid = threadIdx.x;
    int b = blockIdx.x;

    if (tid < 80) pb[tid] = g_PB[b * 80 + tid];
    __syncthreads();

    bool bit = false;
    if (tid < 80) {
        const uint4* fr = (const uint4*)(g_FC1 + tid * 80);
        int cnt = 0;
        #pragma unroll
        for (int k = 0; k < 20; k++) {
            uint4 v = __ldg(&fr[k]);
            cnt += __popc(pb[4 * k]     ^ v.x);
            cnt += __popc(pb[4 * k + 1] ^ v.y);
            cnt += __popc(pb[4 * k + 2] ^ v.z);
            cnt += __popc(pb[4 * k + 3] ^ v.w);
        }
        int dot = 1560 - 2 * cnt;                              // exact integer
        float sc = g3[tid] / sqrtf(v3[tid] + EPS);
        float sb = __fsub_rn(b3[tid], __fmul_rn(m3[tid], sc));
        float y = __fadd_rn(__fmul_rn((float)dot, sc), sb);
        bit = (y > 0.f);                                       // sign(prelu(y)) = sign(y)
    }
    uint32_t bl = __ballot_sync(0xFFFFFFFFu, bit);
    if ((tid & 31) == 0 && tid < 96) hb[tid >> 5] = bl;
    __syncthreads();

    if (tid < 2) {
        int cnt = 0;
        #pragma unroll
        for (int k = 0; k < 3; k++) cnt += __popc(hb[k] ^ g_FC2[tid * 3 + k]);
        out[b * 2 + tid] = (float)(80 - 2 * cnt);              // exact integer
    }
}

// ---------------- launch -----------------------------------------------------
extern "C" void kernel_launch(void* const* d_in, const int* in_sizes, int n_in,
                              void* d_out, int out_size) {
    const float* x    = (const float*)d_in[0];
    const float* w1   = (const float*)d_in[1];
    const float* bn1g = (const float*)d_in[2];
    const float* bn1b = (const float*)d_in[3];
    const float* bn1m = (const float*)d_in[4];
    const float* bn1v = (const float*)d_in[5];
    const float* w2   = (const float*)d_in[7];
    const float* bn2g = (const float*)d_in[8];
    const float* bn2b = (const float*)d_in[9];
    const float* bn2m = (const float*)d_in[10];
    const float* bn2v = (const float*)d_in[11];
    const float* a2   = (const float*)d_in[12];
    const float* fc1  = (const float*)d_in[13];
    const float* bn3g = (const float*)d_in[14];
    const float* bn3b = (const float*)d_in[15];
    const float* bn3m = (const float*)d_in[16];
    const float* bn3v = (const float*)d_in[17];
    const float* fc2  = (const float*)d_in[19];
    float* out = (float*)d_out;

    // 20 pack blocks + 2560 conv blocks in one launch
    ka_conv1<<<2580, 96>>>(x, w1, bn1g, bn1b, bn1m, bn1v, w2, fc1, fc2);

    size_t smemB = (size_t)(12640 + 960 + 40 + 40 + 40) * 4;
    cudaFuncSetAttribute(kb_conv2, cudaFuncAttributeMaxDynamicSharedMemorySize, (int)smemB);
    kb_conv2<<<512, 256, smemB>>>(bn2g, bn2b, bn2m, bn2v, a2);

    kc_fc<<<256, 128>>>(bn3g, bn3b, bn3m, bn3v, out);
}